// round 2
// baseline (speedup 1.0000x reference)
#include <cuda_runtime.h>

#define NC 19
#define BB 8
#define HH 512
#define WIDTH 512
#define HW (HH*WIDTH)
#define WW 16                 // 512 bits per row = 16 u32 words
#define HALO 20
#define STRIP 128
#define RB (STRIP + 2*HALO)   // 168 rows held in smem
#define NSTRIP (HH/STRIP)     // 4
#define NBLK (BB*NC*NSTRIP)   // 608
#define SMEMSZ (RB*WW*4*2 + STRIP*WIDTH + 64)  // A + B masks, int8 dist, reduce pad

// Scratch (static device globals; allocation-free)
__device__ unsigned g_bits[(size_t)BB*NC*HH*WW];   // ~5 MB bit-packed per-class masks
__device__ float    g_max [(size_t)BB*HW];         // 8 MB per-pixel max over classes
__device__ float    g_inv [(size_t)BB*HW];         // 8 MB per-pixel 1/sum(exp)
__device__ float    g_part[NBLK];                  // per-block partial sums

// Fast exp: polynomial 2^f, |rel err| ~3e-6, FMA-pipe only (avoids MUFU bottleneck)
__device__ __forceinline__ float fexp(float x) {
    float y = x * 1.4426950408889634f;
    y = fmaxf(y, -80.0f);                 // inputs are <=0 here; guard underflow
    float z = y + 12582912.0f;            // round-to-nearest via magic number
    int   n = __float_as_int(z) - 0x4B400000;
    float f = y - (z - 12582912.0f);      // f in [-0.5, 0.5]
    float p =          1.3333558e-3f;
    p = fmaf(p, f, 9.6181291e-3f);
    p = fmaf(p, f, 5.5504109e-2f);
    p = fmaf(p, f, 2.4022651e-1f);
    p = fmaf(p, f, 6.9314718e-1f);
    p = fmaf(p, f, 1.0f);
    return __int_as_float(__float_as_int(p) + (n << 23));
}

// K0: per-pixel softmax stats (max, 1/sum(exp)) over the 19 classes
__global__ void k_softmax_stats(const float* __restrict__ pred) {
    int g  = blockIdx.x * blockDim.x + threadIdx.x;   // 0 .. 8*HW-1
    int b  = g >> 18;
    int hw = g & (HW - 1);
    const float* p = pred + (size_t)b * NC * HW + hw;
    float v[NC];
    float m = -1e30f;
#pragma unroll
    for (int c = 0; c < NC; ++c) { v[c] = __ldg(p + (size_t)c * HW); m = fmaxf(m, v[c]); }
    float s = 0.f;
#pragma unroll
    for (int c = 0; c < NC; ++c) s += fexp(v[c] - m);
    g_max[g] = m;
    g_inv[g] = 1.0f / s;
}

// K1: build bit-packed per-class masks via warp ballots (target is int32)
__global__ void k_bits(const int* __restrict__ tgt) {
    int g    = blockIdx.x * blockDim.x + threadIdx.x;
    int lane = g & 31;
    int wid  = g >> 5;                       // 0 .. 65535  = b*8192 + h*16 + ww
    int ww   = wid & 15;
    int h    = (wid >> 4) & 511;
    int b    = wid >> 13;
    int lab  = tgt[(size_t)(b * HH + h) * WIDTH + ww * 32 + lane];
    unsigned my = 0;
#pragma unroll
    for (int c = 0; c < NC; ++c) {
        unsigned bal = __ballot_sync(0xffffffffu, lab == c);
        if (lane == c) my = bal;
    }
    if (lane < NC)
        g_bits[((size_t)(b * NC + lane) * HH + h) * WW + ww] = my;
}

// K2: fused 20-step bitwise dilation (in smem) + signed int8 toggle accumulation
//     + softmax-weighted loss contribution for a 128-row strip of one (b,c) plane.
__global__ void __launch_bounds__(512, 2) k_dilate(const float* __restrict__ pred) {
    extern __shared__ unsigned char sraw[];
    unsigned*    A    = (unsigned*)sraw;               // RB*WW words
    unsigned*    Bv   = A + RB * WW;                   // RB*WW words
    signed char* dist = (signed char*)(Bv + RB * WW);  // STRIP*WIDTH bytes
    float*       red  = (float*)(dist + STRIP * WIDTH);

    int blk = blockIdx.x;
    int s   = blk & 3;
    int t2  = blk >> 2;
    int c   = t2 % NC;
    int b   = t2 / NC;
    int tid = threadIdx.x;
    int g0  = s * STRIP - HALO;

    const unsigned* mbase = g_bits + (size_t)(b * NC + c) * HH * WW;
    for (int idx = tid; idx < RB * WW; idx += 512) {
        int r = idx >> 4;
        int g = g0 + r;
        A[idx] = (g >= 0 && g < HH) ? mbase[(size_t)g * WW + (idx & 15)] : 0u;
    }
    for (int idx = tid * 4; idx < STRIP * WIDTH; idx += 512 * 4)
        *(int*)(dist + idx) = 0;
    __syncthreads();

    unsigned* cur = A;
    unsigned* nxt = Bv;
    for (int it = 0; it < 20; ++it) {
        signed char inc = (signed char)(it + 1);
        for (int idx = tid; idx < RB * WW; idx += 512) {
            int r = idx >> 4, k = idx & 15;
            bool hu = (r > 0), hd = (r < RB - 1);
            unsigned u = hu ? cur[idx - WW] : 0u;
            unsigned d = hd ? cur[idx + WW] : 0u;
            unsigned m = cur[idx];
            unsigned comb = u | m | d;
            unsigned combL = 0u, combR = 0u;
            if (k > 0)
                combL = cur[idx - 1] | (hu ? cur[idx - WW - 1] : 0u) | (hd ? cur[idx + WW - 1] : 0u);
            if (k < WW - 1)
                combR = cur[idx + 1] | (hu ? cur[idx - WW + 1] : 0u) | (hd ? cur[idx + WW + 1] : 0u);
            // neighbors-only OR: verticals + horizontal shifts with cross-word carries
            unsigned dil = (u | d) | __funnelshift_l(combL, comb, 1)
                                   | __funnelshift_r(comb, combR, 1);
            nxt[idx] = dil;
            unsigned tg = dil ^ m;
            if (tg != 0u && r >= HALO && r < RB - HALO) {
                int base = ((r - HALO) << 9) + (k << 5);
                do {
                    int j = __ffs(tg) - 1;
                    tg &= tg - 1;
                    dist[base + j] = (signed char)(dist[base + j] +
                                     (((dil >> j) & 1u) ? (int)inc : -(int)inc));
                } while (tg);
            }
        }
        __syncthreads();
        unsigned* t = cur; cur = nxt; nxt = t;
    }

    // finalize: loss contribution of this strip
    size_t poff = (size_t)(b * NC + c) * HW + (size_t)(s * STRIP) * WIDTH;
    size_t soff = (size_t)b * HW + (size_t)(s * STRIP) * WIDTH;
    const float* pb = pred + poff;
    float acc = 0.f;
    for (int idx = tid; idx < STRIP * WIDTH; idx += 512) {
        int lr = idx >> 9, w = idx & 511;
        unsigned mword = cur[(lr + HALO) * WW + (w >> 5)];
        float dv = ((mword >> (w & 31)) & 1u) ? (float)dist[idx] : 20.0f;
        float pr = fexp(__ldg(pb + idx) - __ldg(g_max + soff + idx)) * __ldg(g_inv + soff + idx);
        acc += pr * dv;
    }
#pragma unroll
    for (int o = 16; o; o >>= 1) acc += __shfl_down_sync(0xffffffffu, acc, o);
    if ((tid & 31) == 0) red[tid >> 5] = acc;
    __syncthreads();
    if (tid < 16) {
        float v = red[tid];
#pragma unroll
        for (int o = 8; o; o >>= 1) v += __shfl_down_sync(0x0000ffffu, v, o);
        if (tid == 0) g_part[blk] = v;
    }
}

// K3: deterministic final reduction of the 608 partials -> mean
__global__ void k_reduce(float* __restrict__ out) {
    __shared__ float red[32];
    int tid = threadIdx.x;
    float v = (tid < NBLK) ? g_part[tid] : 0.f;
#pragma unroll
    for (int o = 16; o; o >>= 1) v += __shfl_down_sync(0xffffffffu, v, o);
    if ((tid & 31) == 0) red[tid >> 5] = v;
    __syncthreads();
    if (tid < 32) {
        float x = (tid < (int)(blockDim.x >> 5)) ? red[tid] : 0.f;
#pragma unroll
        for (int o = 16; o; o >>= 1) x += __shfl_down_sync(0xffffffffu, x, o);
        if (tid == 0) out[0] = x * (1.0f / ((float)BB * NC * HW));
    }
}

extern "C" void kernel_launch(void* const* d_in, const int* in_sizes, int n_in,
                              void* d_out, int out_size) {
    (void)in_sizes; (void)n_in; (void)out_size;
    const float* pred = (const float*)d_in[0];
    const int*   tgt  = (const int*)d_in[1];

    cudaFuncSetAttribute(k_dilate, cudaFuncAttributeMaxDynamicSharedMemorySize, SMEMSZ);

    k_softmax_stats<<<8192, 256>>>(pred);
    k_bits<<<8192, 256>>>(tgt);
    k_dilate<<<NBLK, 512, SMEMSZ>>>(pred);
    k_reduce<<<1, 640>>>((float*)d_out);
}

// round 3
// speedup vs baseline: 1.3070x; 1.3070x over previous
#include <cuda_runtime.h>

#define NC 19
#define BB 8
#define HH 512
#define WIDTH 512
#define HW (HH*WIDTH)
#define WW 16                 // 512 bits per row = 16 u32 words
#define HALO 20
#define STRIP 128
#define RB (STRIP + 2*HALO)   // 168 rows in smem
#define NSTRIP (HH/STRIP)     // 4
#define NBLK (BB*NC*NSTRIP)   // 608
#define NWORDS (RB*WW)        // 2688
#define IWORDS (STRIP*WW)     // 2048 interior words
#define SMEMSZ ((NWORDS*2 + IWORDS*5)*4)   // A + B + 5 count planes = 62464 B

#define NB3 8192              // k_loss blocks

// Scratch (static device globals; allocation-free)
__device__ unsigned       g_bits[(size_t)BB*NC*HH*WW];  // ~5 MB packed class masks
__device__ unsigned char  g_dist[(size_t)BB*NC*HW];     // 40 MB final distance (0..20)
__device__ float          g_part[NB3];                  // per-block loss partials

// Fast exp on the FMA pipe (|rel err| ~3e-6), avoids MUFU throughput limits
__device__ __forceinline__ float fexp(float x) {
    float y = x * 1.4426950408889634f;
    y = fmaxf(y, -80.0f);
    float z = y + 12582912.0f;
    int   n = __float_as_int(z) - 0x4B400000;
    float f = y - (z - 12582912.0f);
    float p =          1.3333558e-3f;
    p = fmaf(p, f, 9.6181291e-3f);
    p = fmaf(p, f, 5.5504109e-2f);
    p = fmaf(p, f, 2.4022651e-1f);
    p = fmaf(p, f, 6.9314718e-1f);
    p = fmaf(p, f, 1.0f);
    return __int_as_float(__float_as_int(p) + (n << 23));
}

// K0: bit-pack per-class masks via warp ballots (target is int32)
__global__ void k_bits(const int* __restrict__ tgt) {
    int g    = blockIdx.x * blockDim.x + threadIdx.x;
    int lane = g & 31;
    int wid  = g >> 5;                 // b*8192 + h*16 + ww
    int ww   = wid & 15;
    int h    = (wid >> 4) & 511;
    int b    = wid >> 13;
    int lab  = tgt[(size_t)(b * HH + h) * WIDTH + ww * 32 + lane];
    unsigned my = 0;
#pragma unroll
    for (int c = 0; c < NC; ++c) {
        unsigned bal = __ballot_sync(0xffffffffu, lab == c);
        if (lane == c) my = bal;
    }
    if (lane < NC)
        g_bits[((size_t)(b * NC + lane) * HH + h) * WW + ww] = my;
}

// K1: bitwise dilation with bit-sliced state-count planes + fixed-point early exit.
//     dist = t*m_final - count  (summation by parts); writes uint8 distances.
__global__ void __launch_bounds__(512, 3) k_dilate() {
    extern __shared__ unsigned sh[];
    unsigned* A  = sh;                  // NWORDS
    unsigned* Bv = sh + NWORDS;         // NWORDS
    unsigned* P  = sh + 2 * NWORDS;     // 5 * IWORDS count bit-planes

    int blk = blockIdx.x;
    int s   = blk & 3;
    int t2  = blk >> 2;
    int c   = t2 % NC;
    int b   = t2 / NC;
    int tid = threadIdx.x;
    int g0  = s * STRIP - HALO;

    const unsigned* mbase = g_bits + (size_t)(b * NC + c) * HH * WW;
    for (int idx = tid; idx < NWORDS; idx += 512) {
        int g = g0 + (idx >> 4);
        A[idx] = (g >= 0 && g < HH) ? mbase[(size_t)g * WW + (idx & 15)] : 0u;
    }
    for (int idx = tid; idx < 5 * IWORDS; idx += 512) P[idx] = 0u;
    __syncthreads();

    unsigned* cur = A;
    unsigned* nxt = Bv;
    int t = 20;
    for (int it = 0; it < 20; ++it) {
        int changed = 0;
        for (int idx = tid; idx < NWORDS; idx += 512) {
            int r = idx >> 4, k = idx & 15;
            bool hu = (r > 0), hd = (r < RB - 1);
            unsigned u = hu ? cur[idx - WW] : 0u;
            unsigned d = hd ? cur[idx + WW] : 0u;
            unsigned m = cur[idx];
            unsigned comb = u | m | d;
            unsigned combL = 0u, combR = 0u;
            if (k > 0)
                combL = cur[idx - 1] | (hu ? cur[idx - WW - 1] : 0u) | (hd ? cur[idx + WW - 1] : 0u);
            if (k < WW - 1)
                combR = cur[idx + 1] | (hu ? cur[idx - WW + 1] : 0u) | (hd ? cur[idx + WW + 1] : 0u);
            unsigned dil = (u | d) | __funnelshift_l(combL, comb, 1)
                                   | __funnelshift_r(comb, combR, 1);
            nxt[idx] = dil;
            changed |= (int)(dil != m);
            // accumulate current state (before-step) into 5-bit bit-sliced counters
            if (idx >= HALO * WW && idx < NWORDS - HALO * WW) {
                int pi = idx - HALO * WW;
                unsigned carry = m;
#pragma unroll
                for (int p = 0; p < 5; ++p) {
                    unsigned tp = P[p * IWORDS + pi];
                    P[p * IWORDS + pi] = tp ^ carry;
                    carry &= tp;
                }
            }
        }
        int any = __syncthreads_or(changed);
        unsigned* tmp = cur; cur = nxt; nxt = tmp;
        if (!any) { t = it + 1; break; }
    }

    // finalize: out byte = m_final ? (t - count) : 20 ; coalesced u32 stores
    unsigned* obase = (unsigned*)(g_dist + ((size_t)(b * NC + c) * HH + s * STRIP) * WIDTH);
    for (int q = tid; q < STRIP * WIDTH / 4; q += 512) {
        int r  = q >> 7;           // 128 u32 per row
        int u  = q & 127;
        int w  = u >> 3;
        int jb = (u & 7) * 4;
        int pi = r * WW + w;
        unsigned mf = cur[(r + HALO) * WW + w];
        unsigned c0 = P[0 * IWORDS + pi], c1 = P[1 * IWORDS + pi],
                 c2 = P[2 * IWORDS + pi], c3 = P[3 * IWORDS + pi],
                 c4 = P[4 * IWORDS + pi];
        unsigned out = 0;
#pragma unroll
        for (int jj = 0; jj < 4; ++jj) {
            int j = jb + jj;
            int cnt = (int)((c0 >> j) & 1u) + (int)(((c1 >> j) & 1u) << 1)
                    + (int)(((c2 >> j) & 1u) << 2) + (int)(((c3 >> j) & 1u) << 3)
                    + (int)(((c4 >> j) & 1u) << 4);
            int v = ((mf >> j) & 1u) ? (t - cnt) : 20;
            out |= (unsigned)v << (jj * 8);
        }
        obase[q] = out;
    }
}

// K2: fused softmax + distance dot per pixel; single pred read
__global__ void k_loss(const float* __restrict__ pred) {
    __shared__ float red[8];
    int g  = blockIdx.x * 256 + threadIdx.x;
    int b  = g >> 18;
    int hw = g & (HW - 1);
    const float*         p  = pred   + (size_t)b * NC * HW + hw;
    const unsigned char* dp = g_dist + (size_t)b * NC * HW + hw;
    float v[NC];
    float m = -1e30f;
#pragma unroll
    for (int c = 0; c < NC; ++c) { v[c] = __ldg(p + (size_t)c * HW); m = fmaxf(m, v[c]); }
    float se = 0.f, sd = 0.f;
#pragma unroll
    for (int c = 0; c < NC; ++c) {
        float e = fexp(v[c] - m);
        se += e;
        sd = fmaf(e, (float)__ldg(dp + (size_t)c * HW), sd);
    }
    float acc = __fdividef(sd, se);
#pragma unroll
    for (int o = 16; o; o >>= 1) acc += __shfl_down_sync(0xffffffffu, acc, o);
    int tid = threadIdx.x;
    if ((tid & 31) == 0) red[tid >> 5] = acc;
    __syncthreads();
    if (tid < 8) {
        float x = red[tid];
#pragma unroll
        for (int o = 4; o; o >>= 1) x += __shfl_down_sync(0x000000ffu, x, o);
        if (tid == 0) g_part[blockIdx.x] = x;
    }
}

// K3: deterministic final reduction of 8192 partials -> mean
__global__ void k_reduce(float* __restrict__ out) {
    __shared__ float red[32];
    int tid = threadIdx.x;
    float v = 0.f;
#pragma unroll
    for (int i = 0; i < NB3 / 1024; ++i) v += g_part[tid + i * 1024];
#pragma unroll
    for (int o = 16; o; o >>= 1) v += __shfl_down_sync(0xffffffffu, v, o);
    if ((tid & 31) == 0) red[tid >> 5] = v;
    __syncthreads();
    if (tid < 32) {
        float x = red[tid];
#pragma unroll
        for (int o = 16; o; o >>= 1) x += __shfl_down_sync(0xffffffffu, x, o);
        if (tid == 0) out[0] = x * (1.0f / ((float)BB * NC * HW));
    }
}

extern "C" void kernel_launch(void* const* d_in, const int* in_sizes, int n_in,
                              void* d_out, int out_size) {
    (void)in_sizes; (void)n_in; (void)out_size;
    const float* pred = (const float*)d_in[0];
    const int*   tgt  = (const int*)d_in[1];

    cudaFuncSetAttribute(k_dilate, cudaFuncAttributeMaxDynamicSharedMemorySize, SMEMSZ);

    k_bits<<<8192, 256>>>(tgt);
    k_dilate<<<NBLK, 512, SMEMSZ>>>();
    k_loss<<<NB3, 256>>>(pred);
    k_reduce<<<1, 1024>>>((float*)d_out);
}